// round 8
// baseline (speedup 1.0000x reference)
#include <cuda_runtime.h>
#include <cuda_bf16.h>
#include <cuda_fp16.h>
#include <math_constants.h>
#include <cstdint>
#include <cstring>

#define BATCH 4
#define SEQ   2048
#define CDIM  1024
#define NHEAD 16
#define HDIM  64
#define N3C   3072

__device__ float g_Q[BATCH * NHEAD * SEQ * HDIM];
__device__ float g_K[BATCH * NHEAD * SEQ * HDIM];
__device__ float g_V[BATCH * NHEAD * SEQ * HDIM];
__device__ float g_O[BATCH * NHEAD * SEQ * HDIM];

// ---------------------------------------------------------------------------
// helpers
// ---------------------------------------------------------------------------
__device__ __forceinline__ uint32_t f2tf32(float f) {
    uint32_t r;
    asm("cvt.rna.tf32.f32 %0, %1;" : "=r"(r) : "f"(f));
    return r;
}

__device__ __forceinline__ uint32_t h2u(__half2 h) {
    uint32_t r;
    memcpy(&r, &h, 4);
    return r;
}

__device__ __forceinline__ void mma_tf32(float c[4],
                                         const uint32_t a[4],
                                         uint32_t b0, uint32_t b1) {
    asm volatile(
        "mma.sync.aligned.m16n8k8.row.col.f32.tf32.tf32.f32 "
        "{%0,%1,%2,%3}, {%4,%5,%6,%7}, {%8,%9}, {%0,%1,%2,%3};\n"
        : "+f"(c[0]), "+f"(c[1]), "+f"(c[2]), "+f"(c[3])
        : "r"(a[0]), "r"(a[1]), "r"(a[2]), "r"(a[3]),
          "r"(b0), "r"(b1));
}

__device__ __forceinline__ void mma_f16(float c[4],
                                        const uint32_t a[4],
                                        uint32_t b0, uint32_t b1) {
    asm volatile(
        "mma.sync.aligned.m16n8k16.row.col.f32.f16.f16.f32 "
        "{%0,%1,%2,%3}, {%4,%5,%6,%7}, {%8,%9}, {%0,%1,%2,%3};\n"
        : "+f"(c[0]), "+f"(c[1]), "+f"(c[2]), "+f"(c[3])
        : "r"(a[0]), "r"(a[1]), "r"(a[2]), "r"(a[3]),
          "r"(b0), "r"(b1));
}

#define PAD 136   // 128 + 8: 8-bank skew per k-row -> conflict-free frag LDS

// ---------------------------------------------------------------------------
// Kernel 1: QKV GEMM, tf32 mma. 128x128 CTA tile, BK=16, 128 threads,
// 4 warps (2x2), 64x64 per warp (4 Mt x 8 Nt m16n8k8). Double-buffered.
// ---------------------------------------------------------------------------
__global__ __launch_bounds__(128) void qkv_gemm(
    const float* __restrict__ X,    // [8192, 1024]
    const float* __restrict__ W,    // [1024, 3072]
    const float* __restrict__ bias) // [3072]
{
    __shared__ uint32_t As[2][16][PAD];   // [k][m]
    __shared__ uint32_t Bs[2][16][PAD];   // [k][n]

    const int tid = threadIdx.x;
    const int wid = tid >> 5;
    const int lane = tid & 31;
    const int g = lane >> 2;          // 0..7
    const int tig = lane & 3;         // 0..3
    const int warp_m = wid >> 1;      // 0..1 -> 64 rows
    const int warp_n = wid & 1;       // 0..1 -> 64 cols

    const int bm = blockIdx.y * 128;
    const int bn = blockIdx.x * 128;

    // A: each thread owns full k-row of its M-row (tid = row 0..127)
    const float* Ap = X + (size_t)(bm + tid) * CDIM;
    // B: warp w owns k-rows {w, w+4, w+8, w+12}; lane covers 4 n-cols
    const int bc = lane * 4;
    const float* Bp = W + (size_t)wid * N3C + bn + bc;

    float acc[4][8][4];
    #pragma unroll
    for (int mt = 0; mt < 4; mt++)
        #pragma unroll
        for (int nt = 0; nt < 8; nt++)
            #pragma unroll
            for (int i = 0; i < 4; i++) acc[mt][nt][i] = 0.f;

    float4 aN[4], bN[4];
    auto ldg = [&](int k0) {
        #pragma unroll
        for (int j = 0; j < 4; j++) {
            aN[j] = *(const float4*)(Ap + k0 + j * 4);
            bN[j] = *(const float4*)(Bp + (size_t)(k0 + j * 4) * N3C);
        }
    };
    auto stage = [&](int buf) {
        #pragma unroll
        for (int j = 0; j < 4; j++) {
            As[buf][j * 4 + 0][tid] = f2tf32(aN[j].x);
            As[buf][j * 4 + 1][tid] = f2tf32(aN[j].y);
            As[buf][j * 4 + 2][tid] = f2tf32(aN[j].z);
            As[buf][j * 4 + 3][tid] = f2tf32(aN[j].w);
            uint4 pb = make_uint4(f2tf32(bN[j].x), f2tf32(bN[j].y),
                                  f2tf32(bN[j].z), f2tf32(bN[j].w));
            *(uint4*)&Bs[buf][wid + j * 4][bc] = pb;
        }
    };

    ldg(0);
    stage(0);
    __syncthreads();

    const int am = warp_m * 64;
    const int an = warp_n * 64;

    int cur = 0;
    for (int k0 = 0; k0 < CDIM; k0 += 16) {
        const bool has_next = (k0 + 16) < CDIM;
        if (has_next) ldg(k0 + 16);

        #pragma unroll
        for (int kk = 0; kk < 16; kk += 8) {
            uint32_t Af[4][4], Bf[8][2];
            #pragma unroll
            for (int mt = 0; mt < 4; mt++) {
                const int m0 = am + mt * 16;
                Af[mt][0] = As[cur][kk + tig][m0 + g];
                Af[mt][1] = As[cur][kk + tig][m0 + g + 8];
                Af[mt][2] = As[cur][kk + tig + 4][m0 + g];
                Af[mt][3] = As[cur][kk + tig + 4][m0 + g + 8];
            }
            #pragma unroll
            for (int nt = 0; nt < 8; nt++) {
                const int n0 = an + nt * 8;
                Bf[nt][0] = Bs[cur][kk + tig][n0 + g];
                Bf[nt][1] = Bs[cur][kk + tig + 4][n0 + g];
            }
            #pragma unroll
            for (int mt = 0; mt < 4; mt++)
                #pragma unroll
                for (int nt = 0; nt < 8; nt++)
                    mma_tf32(acc[mt][nt], Af[mt], Bf[nt][0], Bf[nt][1]);
        }

        if (has_next) {
            const int nxt = cur ^ 1;
            stage(nxt);
            __syncthreads();
            cur = nxt;
        }
    }

    // Epilogue: scatter into g_Q / g_K / g_V (Q pre-scaled by 0.125)
    #pragma unroll
    for (int mt = 0; mt < 4; mt++) {
        #pragma unroll
        for (int half = 0; half < 2; half++) {
            const int row = bm + am + mt * 16 + g + half * 8;
            const int bb = row >> 11;
            const int t  = row & 2047;
            #pragma unroll
            for (int nt = 0; nt < 8; nt++) {
                const int col = bn + an + nt * 8 + tig * 2;
                float v0 = acc[mt][nt][half * 2 + 0] + bias[col];
                float v1 = acc[mt][nt][half * 2 + 1] + bias[col + 1];
                const int part = col >> 10;
                const int cc = col & 1023;
                const int h = cc >> 6;
                const int d = cc & 63;
                if (part == 0) { v0 *= 0.125f; v1 *= 0.125f; }
                float* dst = (part == 0) ? g_Q : ((part == 1) ? g_K : g_V);
                const int idx = ((bb * NHEAD + h) * SEQ + t) * HDIM + d;
                *(float2*)&dst[idx] = make_float2(v0, v1);
            }
        }
    }
}

// ---------------------------------------------------------------------------
// Kernel 2: tensor-core causal flash attention (unchanged from R7 pass).
// ---------------------------------------------------------------------------
#define KSTRIDE 68   // Ks row stride (floats)
#define VSTRIDE 72   // VsT row stride (halves)

__global__ __launch_bounds__(256) void attn_kernel()
{
    const int bh  = blockIdx.y;
    const int qt  = (SEQ / 128 - 1) - blockIdx.x;
    const int tid = threadIdx.x;
    const int wid = tid >> 5;
    const int lane = tid & 31;
    const int g   = lane >> 2;
    const int tig = lane & 3;

    const int qbase = qt * 128;
    const int wbase = qbase + wid * 16;
    const int row0  = wbase + g;
    const int row1  = row0 + 8;

    __shared__ uint32_t Ks[64][KSTRIDE];
    __shared__ __half   VsT[64][VSTRIDE];

    const float* Qb = g_Q + (size_t)bh * SEQ * HDIM;
    const float* Kb = g_K + (size_t)bh * SEQ * HDIM;
    const float* Vb = g_V + (size_t)bh * SEQ * HDIM;

    uint32_t qf[8][4];
    #pragma unroll
    for (int kt8 = 0; kt8 < 8; kt8++) {
        qf[kt8][0] = f2tf32(Qb[(size_t)row0 * HDIM + kt8 * 8 + tig]);
        qf[kt8][1] = f2tf32(Qb[(size_t)row1 * HDIM + kt8 * 8 + tig]);
        qf[kt8][2] = f2tf32(Qb[(size_t)row0 * HDIM + kt8 * 8 + tig + 4]);
        qf[kt8][3] = f2tf32(Qb[(size_t)row1 * HDIM + kt8 * 8 + tig + 4]);
    }

    float of[8][4];
    #pragma unroll
    for (int dt = 0; dt < 8; dt++)
        #pragma unroll
        for (int i = 0; i < 4; i++) of[dt][i] = 0.f;

    float m0 = -CUDART_INF_F, m1 = -CUDART_INF_F;
    float l0 = 0.f, l1 = 0.f;

    const int ktmax = (qbase + 127) >> 6;

    for (int kt = 0; kt <= ktmax; kt++) {
        __syncthreads();
        #pragma unroll
        for (int i = 0; i < 4; i++) {
            const int idx = tid + i * 256;
            const int key = idx >> 4;
            const int c4  = (idx & 15) * 4;
            const size_t gidx = (size_t)(kt * 64 + key) * HDIM + c4;
            float4 kv = *(const float4*)(Kb + gidx);
            uint32_t* kd = &Ks[key][c4];
            kd[0] = f2tf32(kv.x); kd[1] = f2tf32(kv.y);
            kd[2] = f2tf32(kv.z); kd[3] = f2tf32(kv.w);
            float4 vv = *(const float4*)(Vb + gidx);
            VsT[c4 + 0][key] = __float2half(vv.x);
            VsT[c4 + 1][key] = __float2half(vv.y);
            VsT[c4 + 2][key] = __float2half(vv.z);
            VsT[c4 + 3][key] = __float2half(vv.w);
        }
        __syncthreads();

        if (kt * 64 > wbase + 15) continue;

        float sf[8][4];
        #pragma unroll
        for (int nt = 0; nt < 8; nt++) {
            sf[nt][0] = sf[nt][1] = sf[nt][2] = sf[nt][3] = 0.f;
            const int kr = nt * 8 + g;
            #pragma unroll
            for (int kt8 = 0; kt8 < 8; kt8++) {
                uint32_t b0 = Ks[kr][kt8 * 8 + tig];
                uint32_t b1 = Ks[kr][kt8 * 8 + tig + 4];
                mma_tf32(sf[nt], qf[kt8], b0, b1);
            }
        }

        const int colbase = kt * 64;
        if (colbase + 63 > wbase) {
            #pragma unroll
            for (int nt = 0; nt < 8; nt++) {
                const int c = colbase + nt * 8 + tig * 2;
                if (c     > row0) sf[nt][0] = -CUDART_INF_F;
                if (c + 1 > row0) sf[nt][1] = -CUDART_INF_F;
                if (c     > row1) sf[nt][2] = -CUDART_INF_F;
                if (c + 1 > row1) sf[nt][3] = -CUDART_INF_F;
            }
        }

        float t0 = -CUDART_INF_F, t1 = -CUDART_INF_F;
        #pragma unroll
        for (int nt = 0; nt < 8; nt++) {
            t0 = fmaxf(t0, fmaxf(sf[nt][0], sf[nt][1]));
            t1 = fmaxf(t1, fmaxf(sf[nt][2], sf[nt][3]));
        }
        t0 = fmaxf(t0, __shfl_xor_sync(0xffffffffu, t0, 1));
        t0 = fmaxf(t0, __shfl_xor_sync(0xffffffffu, t0, 2));
        t1 = fmaxf(t1, __shfl_xor_sync(0xffffffffu, t1, 1));
        t1 = fmaxf(t1, __shfl_xor_sync(0xffffffffu, t1, 2));

        const float mn0 = fmaxf(m0, t0);
        const float mn1 = fmaxf(m1, t1);
        const float al0 = __expf(m0 - mn0);
        const float al1 = __expf(m1 - mn1);
        m0 = mn0; m1 = mn1;
        l0 *= al0; l1 *= al1;
        #pragma unroll
        for (int dt = 0; dt < 8; dt++) {
            of[dt][0] *= al0; of[dt][1] *= al0;
            of[dt][2] *= al1; of[dt][3] *= al1;
        }

        uint32_t pa[4][4];
        #pragma unroll
        for (int nt = 0; nt < 8; nt++) {
            const float p0 = __expf(sf[nt][0] - m0);
            const float p1 = __expf(sf[nt][1] - m0);
            const float p2 = __expf(sf[nt][2] - m1);
            const float p3 = __expf(sf[nt][3] - m1);
            l0 += p0 + p1;
            l1 += p2 + p3;
            const uint32_t lo = h2u(__floats2half2_rn(p0, p1));
            const uint32_t hi = h2u(__floats2half2_rn(p2, p3));
            const int kc  = nt >> 1;
            if ((nt & 1) == 0) { pa[kc][0] = lo; pa[kc][1] = hi; }
            else               { pa[kc][2] = lo; pa[kc][3] = hi; }
        }

        #pragma unroll
        for (int dt = 0; dt < 8; dt++) {
            const int dr = dt * 8 + g;
            #pragma unroll
            for (int kc = 0; kc < 4; kc++) {
                uint32_t b0 = *(const uint32_t*)&VsT[dr][kc * 16 + tig * 2];
                uint32_t b1 = *(const uint32_t*)&VsT[dr][kc * 16 + tig * 2 + 8];
                mma_f16(of[dt], pa[kc], b0, b1);
            }
        }
    }

    l0 += __shfl_xor_sync(0xffffffffu, l0, 1);
    l0 += __shfl_xor_sync(0xffffffffu, l0, 2);
    l1 += __shfl_xor_sync(0xffffffffu, l1, 1);
    l1 += __shfl_xor_sync(0xffffffffu, l1, 2);
    const float inv0 = 1.0f / l0;
    const float inv1 = 1.0f / l1;

    float* Ob = g_O + (size_t)bh * SEQ * HDIM;
    #pragma unroll
    for (int dt = 0; dt < 8; dt++) {
        const int col = dt * 8 + tig * 2;
        *(float2*)&Ob[(size_t)row0 * HDIM + col] =
            make_float2(of[dt][0] * inv0, of[dt][1] * inv0);
        *(float2*)&Ob[(size_t)row1 * HDIM + col] =
            make_float2(of[dt][2] * inv1, of[dt][3] * inv1);
    }
}

// ---------------------------------------------------------------------------
// Kernel 3: output projection, same 64x64-warp-tile structure; A gathered
// from g_O [B,H,T,D].
// ---------------------------------------------------------------------------
__global__ __launch_bounds__(128) void out_gemm(
    const float* __restrict__ W,    // [1024, 1024]
    const float* __restrict__ bias, // [1024]
    float* __restrict__ out)        // [8192, 1024]
{
    __shared__ uint32_t As[2][16][PAD];
    __shared__ uint32_t Bs[2][16][PAD];

    const int tid = threadIdx.x;
    const int wid = tid >> 5;
    const int lane = tid & 31;
    const int g = lane >> 2;
    const int tig = lane & 3;
    const int warp_m = wid >> 1;
    const int warp_n = wid & 1;

    const int bm = blockIdx.y * 128;
    const int bn = blockIdx.x * 128;

    const int arow = bm + tid;
    const int bb = arow >> 11;
    const int t  = arow & 2047;

    const int bc = lane * 4;
    const float* Bp = W + (size_t)wid * CDIM + bn + bc;

    float acc[4][8][4];
    #pragma unroll
    for (int mt = 0; mt < 4; mt++)
        #pragma unroll
        for (int nt = 0; nt < 8; nt++)
            #pragma unroll
            for (int i = 0; i < 4; i++) acc[mt][nt][i] = 0.f;

    float4 aN[4], bN[4];
    auto ldg = [&](int k0) {
        #pragma unroll
        for (int j = 0; j < 4; j++) {
            const int k = k0 + j * 4;
            const int h = k >> 6;
            const int d = k & 63;
            aN[j] = *(const float4*)&g_O[((bb * NHEAD + h) * SEQ + t) * HDIM + d];
            bN[j] = *(const float4*)(Bp + (size_t)k * CDIM);
        }
    };
    auto stage = [&](int buf) {
        #pragma unroll
        for (int j = 0; j < 4; j++) {
            As[buf][j * 4 + 0][tid] = f2tf32(aN[j].x);
            As[buf][j * 4 + 1][tid] = f2tf32(aN[j].y);
            As[buf][j * 4 + 2][tid] = f2tf32(aN[j].z);
            As[buf][j * 4 + 3][tid] = f2tf32(aN[j].w);
            uint4 pb = make_uint4(f2tf32(bN[j].x), f2tf32(bN[j].y),
                                  f2tf32(bN[j].z), f2tf32(bN[j].w));
            *(uint4*)&Bs[buf][wid + j * 4][bc] = pb;
        }
    };

    ldg(0);
    stage(0);
    __syncthreads();

    const int am = warp_m * 64;
    const int an = warp_n * 64;

    int cur = 0;
    for (int k0 = 0; k0 < CDIM; k0 += 16) {
        const bool has_next = (k0 + 16) < CDIM;
        if (has_next) ldg(k0 + 16);

        #pragma unroll
        for (int kk = 0; kk < 16; kk += 8) {
            uint32_t Af[4][4], Bf[8][2];
            #pragma unroll
            for (int mt = 0; mt < 4; mt++) {
                const int m0 = am + mt * 16;
                Af[mt][0] = As[cur][kk + tig][m0 + g];
                Af[mt][1] = As[cur][kk + tig][m0 + g + 8];
                Af[mt][2] = As[cur][kk + tig + 4][m0 + g];
                Af[mt][3] = As[cur][kk + tig + 4][m0 + g + 8];
            }
            #pragma unroll
            for (int nt = 0; nt < 8; nt++) {
                const int n0 = an + nt * 8;
                Bf[nt][0] = Bs[cur][kk + tig][n0 + g];
                Bf[nt][1] = Bs[cur][kk + tig + 4][n0 + g];
            }
            #pragma unroll
            for (int mt = 0; mt < 4; mt++)
                #pragma unroll
                for (int nt = 0; nt < 8; nt++)
                    mma_tf32(acc[mt][nt], Af[mt], Bf[nt][0], Bf[nt][1]);
        }

        if (has_next) {
            const int nxt = cur ^ 1;
            stage(nxt);
            __syncthreads();
            cur = nxt;
        }
    }

    #pragma unroll
    for (int mt = 0; mt < 4; mt++) {
        #pragma unroll
        for (int half = 0; half < 2; half++) {
            const int row = bm + am + mt * 16 + g + half * 8;
            #pragma unroll
            for (int nt = 0; nt < 8; nt++) {
                const int col = bn + an + nt * 8 + tig * 2;
                float v0 = acc[mt][nt][half * 2 + 0] + bias[col];
                float v1 = acc[mt][nt][half * 2 + 1] + bias[col + 1];
                *(float2*)&out[(size_t)row * CDIM + col] = make_float2(v0, v1);
            }
        }
    }
}

// ---------------------------------------------------------------------------
extern "C" void kernel_launch(void* const* d_in, const int* in_sizes, int n_in,
                              void* d_out, int out_size)
{
    const float* x     = (const float*)d_in[0];
    const float* W_qkv = (const float*)d_in[1];
    const float* b_qkv = (const float*)d_in[2];
    const float* W_out = (const float*)d_in[3];
    const float* b_out = (const float*)d_in[4];
    float* out = (float*)d_out;

    qkv_gemm<<<dim3(N3C / 128, (BATCH * SEQ) / 128), 128>>>(x, W_qkv, b_qkv);
    attn_kernel<<<dim3(SEQ / 128, BATCH * NHEAD), 256>>>();
    out_gemm<<<dim3(CDIM / 128, (BATCH * SEQ) / 128), 128>>>(W_out, b_out, out);
}

// round 10
// speedup vs baseline: 1.1143x; 1.1143x over previous
#include <cuda_runtime.h>
#include <cuda_bf16.h>
#include <cuda_fp16.h>
#include <math_constants.h>
#include <cstdint>
#include <cstring>

#define BATCH 4
#define SEQ   2048
#define CDIM  1024
#define NHEAD 16
#define HDIM  64
#define N3C   3072

__device__ float g_Q[BATCH * NHEAD * SEQ * HDIM];
__device__ float g_K[BATCH * NHEAD * SEQ * HDIM];
__device__ float g_V[BATCH * NHEAD * SEQ * HDIM];
__device__ float g_O[BATCH * NHEAD * SEQ * HDIM];

// ---------------------------------------------------------------------------
// helpers
// ---------------------------------------------------------------------------
__device__ __forceinline__ uint32_t f2tf32(float f) {
    uint32_t r;
    asm("cvt.rna.tf32.f32 %0, %1;" : "=r"(r) : "f"(f));
    return r;
}

__device__ __forceinline__ uint32_t h2u(__half2 h) {
    uint32_t r;
    memcpy(&r, &h, 4);
    return r;
}

__device__ __forceinline__ void cp16(void* smem, const void* gmem) {
    uint32_t s = (uint32_t)__cvta_generic_to_shared(smem);
    asm volatile("cp.async.cg.shared.global [%0], [%1], 16;"
                 :: "r"(s), "l"(gmem) : "memory");
}
#define CP_COMMIT() asm volatile("cp.async.commit_group;" ::: "memory")
#define CP_WAIT0()  asm volatile("cp.async.wait_group 0;" ::: "memory")

__device__ __forceinline__ void mma_tf32(float c[4],
                                         const uint32_t a[4],
                                         uint32_t b0, uint32_t b1) {
    asm volatile(
        "mma.sync.aligned.m16n8k8.row.col.f32.tf32.tf32.f32 "
        "{%0,%1,%2,%3}, {%4,%5,%6,%7}, {%8,%9}, {%0,%1,%2,%3};\n"
        : "+f"(c[0]), "+f"(c[1]), "+f"(c[2]), "+f"(c[3])
        : "r"(a[0]), "r"(a[1]), "r"(a[2]), "r"(a[3]),
          "r"(b0), "r"(b1));
}

__device__ __forceinline__ void mma_f16(float c[4],
                                        const uint32_t a[4],
                                        uint32_t b0, uint32_t b1) {
    asm volatile(
        "mma.sync.aligned.m16n8k16.row.col.f32.f16.f16.f32 "
        "{%0,%1,%2,%3}, {%4,%5,%6,%7}, {%8,%9}, {%0,%1,%2,%3};\n"
        : "+f"(c[0]), "+f"(c[1]), "+f"(c[2]), "+f"(c[3])
        : "r"(a[0]), "r"(a[1]), "r"(a[2]), "r"(a[3]),
          "r"(b0), "r"(b1));
}

#define PAD  136   // B smem row stride (floats): banks 8*tig+g bijective
#define ASTR 20    // A smem row stride (floats): bases 20g mod 32 all distinct

// ---------------------------------------------------------------------------
// Kernel 1: QKV GEMM, tf32 mma, 128x128 CTA tile, BK=16, 256 threads,
// 8 warps (4Mx2N), 32x64 per warp. cp.async.cg staging (raw f32, cvt at
// fragment load). Double-buffered.
// ---------------------------------------------------------------------------
__global__ __launch_bounds__(256) void qkv_gemm(
    const float* __restrict__ X,    // [8192, 1024]
    const float* __restrict__ W,    // [1024, 3072]
    const float* __restrict__ bias) // [3072]
{
    __shared__ float As[2][128][ASTR];   // [m][k] raw f32
    __shared__ float Bs[2][16][PAD];     // [k][n] raw f32

    const int tid = threadIdx.x;
    const int wid = tid >> 5;
    const int lane = tid & 31;
    const int g = lane >> 2;          // 0..7
    const int tig = lane & 3;         // 0..3
    const int warp_m = wid >> 1;      // 0..3
    const int warp_n = wid & 1;       // 0..1

    const int bm = blockIdx.y * 128;
    const int bn = blockIdx.x * 128;

    const int ar = tid >> 2;          // 0..63 (A rows ar, ar+64)
    const int ac = (tid & 3) * 4;     // k offset {0,4,8,12}
    const int br = tid >> 5;          // 0..7 (B k-rows br, br+8)
    const int bc = (tid & 31) * 4;    // n offset

    const float* Ap0 = X + (size_t)(bm + ar) * CDIM + ac;
    const float* Ap1 = X + (size_t)(bm + ar + 64) * CDIM + ac;
    const float* Bp0 = W + (size_t)br * N3C + bn + bc;
    const float* Bp1 = W + (size_t)(br + 8) * N3C + bn + bc;

    float acc[2][8][4];
    #pragma unroll
    for (int mt = 0; mt < 2; mt++)
        #pragma unroll
        for (int nt = 0; nt < 8; nt++)
            #pragma unroll
            for (int i = 0; i < 4; i++) acc[mt][nt][i] = 0.f;

    auto issue_cp = [&](int buf, int k0) {
        cp16(&As[buf][ar][ac],      Ap0 + k0);
        cp16(&As[buf][ar + 64][ac], Ap1 + k0);
        cp16(&Bs[buf][br][bc],      Bp0 + (size_t)k0 * N3C);
        cp16(&Bs[buf][br + 8][bc],  Bp1 + (size_t)k0 * N3C);
        CP_COMMIT();
    };

    issue_cp(0, 0);
    CP_WAIT0();
    __syncthreads();

    const int am = warp_m * 32;
    const int an = warp_n * 64;

    int cur = 0;
    for (int k0 = 0; k0 < CDIM; k0 += 16) {
        const bool has_next = (k0 + 16) < CDIM;
        if (has_next) issue_cp(cur ^ 1, k0 + 16);

        #pragma unroll
        for (int kk = 0; kk < 16; kk += 8) {
            uint32_t Af[2][4], Bf[8][2];
            #pragma unroll
            for (int mt = 0; mt < 2; mt++) {
                const int m0 = am + mt * 16;
                Af[mt][0] = f2tf32(As[cur][m0 + g][kk + tig]);
                Af[mt][1] = f2tf32(As[cur][m0 + g + 8][kk + tig]);
                Af[mt][2] = f2tf32(As[cur][m0 + g][kk + tig + 4]);
                Af[mt][3] = f2tf32(As[cur][m0 + g + 8][kk + tig + 4]);
            }
            #pragma unroll
            for (int nt = 0; nt < 8; nt++) {
                const int n0 = an + nt * 8;
                Bf[nt][0] = f2tf32(Bs[cur][kk + tig][n0 + g]);
                Bf[nt][1] = f2tf32(Bs[cur][kk + tig + 4][n0 + g]);
            }
            #pragma unroll
            for (int mt = 0; mt < 2; mt++)
                #pragma unroll
                for (int nt = 0; nt < 8; nt++)
                    mma_tf32(acc[mt][nt], Af[mt], Bf[nt][0], Bf[nt][1]);
        }

        if (has_next) {
            CP_WAIT0();
            __syncthreads();
            cur ^= 1;
        }
    }

    // Epilogue: scatter into g_Q / g_K / g_V (Q pre-scaled by 0.125)
    #pragma unroll
    for (int mt = 0; mt < 2; mt++) {
        #pragma unroll
        for (int half = 0; half < 2; half++) {
            const int row = bm + am + mt * 16 + g + half * 8;
            const int bb = row >> 11;
            const int t  = row & 2047;
            #pragma unroll
            for (int nt = 0; nt < 8; nt++) {
                const int col = bn + an + nt * 8 + tig * 2;
                float v0 = acc[mt][nt][half * 2 + 0] + bias[col];
                float v1 = acc[mt][nt][half * 2 + 1] + bias[col + 1];
                const int part = col >> 10;      // 0=Q 1=K 2=V
                const int cc = col & 1023;
                const int h = cc >> 6;
                const int d = cc & 63;
                if (part == 0) { v0 *= 0.125f; v1 *= 0.125f; }
                float* dst = (part == 0) ? g_Q : ((part == 1) ? g_K : g_V);
                const int idx = ((bb * NHEAD + h) * SEQ + t) * HDIM + d;
                *(float2*)&dst[idx] = make_float2(v0, v1);
            }
        }
    }
}

// ---------------------------------------------------------------------------
// Kernel 2: tensor-core causal flash attention (unchanged from R7 pass).
// ---------------------------------------------------------------------------
#define KSTRIDE 68   // Ks row stride (floats)
#define VSTRIDE 72   // VsT row stride (halves)

__global__ __launch_bounds__(256) void attn_kernel()
{
    const int bh  = blockIdx.y;
    const int qt  = (SEQ / 128 - 1) - blockIdx.x;
    const int tid = threadIdx.x;
    const int wid = tid >> 5;
    const int lane = tid & 31;
    const int g   = lane >> 2;
    const int tig = lane & 3;

    const int qbase = qt * 128;
    const int wbase = qbase + wid * 16;
    const int row0  = wbase + g;
    const int row1  = row0 + 8;

    __shared__ uint32_t Ks[64][KSTRIDE];
    __shared__ __half   VsT[64][VSTRIDE];

    const float* Qb = g_Q + (size_t)bh * SEQ * HDIM;
    const float* Kb = g_K + (size_t)bh * SEQ * HDIM;
    const float* Vb = g_V + (size_t)bh * SEQ * HDIM;

    uint32_t qf[8][4];
    #pragma unroll
    for (int kt8 = 0; kt8 < 8; kt8++) {
        qf[kt8][0] = f2tf32(Qb[(size_t)row0 * HDIM + kt8 * 8 + tig]);
        qf[kt8][1] = f2tf32(Qb[(size_t)row1 * HDIM + kt8 * 8 + tig]);
        qf[kt8][2] = f2tf32(Qb[(size_t)row0 * HDIM + kt8 * 8 + tig + 4]);
        qf[kt8][3] = f2tf32(Qb[(size_t)row1 * HDIM + kt8 * 8 + tig + 4]);
    }

    float of[8][4];
    #pragma unroll
    for (int dt = 0; dt < 8; dt++)
        #pragma unroll
        for (int i = 0; i < 4; i++) of[dt][i] = 0.f;

    float m0 = -CUDART_INF_F, m1 = -CUDART_INF_F;
    float l0 = 0.f, l1 = 0.f;

    const int ktmax = (qbase + 127) >> 6;

    for (int kt = 0; kt <= ktmax; kt++) {
        __syncthreads();
        #pragma unroll
        for (int i = 0; i < 4; i++) {
            const int idx = tid + i * 256;
            const int key = idx >> 4;
            const int c4  = (idx & 15) * 4;
            const size_t gidx = (size_t)(kt * 64 + key) * HDIM + c4;
            float4 kv = *(const float4*)(Kb + gidx);
            uint32_t* kd = &Ks[key][c4];
            kd[0] = f2tf32(kv.x); kd[1] = f2tf32(kv.y);
            kd[2] = f2tf32(kv.z); kd[3] = f2tf32(kv.w);
            float4 vv = *(const float4*)(Vb + gidx);
            VsT[c4 + 0][key] = __float2half(vv.x);
            VsT[c4 + 1][key] = __float2half(vv.y);
            VsT[c4 + 2][key] = __float2half(vv.z);
            VsT[c4 + 3][key] = __float2half(vv.w);
        }
        __syncthreads();

        if (kt * 64 > wbase + 15) continue;

        float sf[8][4];
        #pragma unroll
        for (int nt = 0; nt < 8; nt++) {
            sf[nt][0] = sf[nt][1] = sf[nt][2] = sf[nt][3] = 0.f;
            const int kr = nt * 8 + g;
            #pragma unroll
            for (int kt8 = 0; kt8 < 8; kt8++) {
                uint32_t b0 = Ks[kr][kt8 * 8 + tig];
                uint32_t b1 = Ks[kr][kt8 * 8 + tig + 4];
                mma_tf32(sf[nt], qf[kt8], b0, b1);
            }
        }

        const int colbase = kt * 64;
        if (colbase + 63 > wbase) {
            #pragma unroll
            for (int nt = 0; nt < 8; nt++) {
                const int c = colbase + nt * 8 + tig * 2;
                if (c     > row0) sf[nt][0] = -CUDART_INF_F;
                if (c + 1 > row0) sf[nt][1] = -CUDART_INF_F;
                if (c     > row1) sf[nt][2] = -CUDART_INF_F;
                if (c + 1 > row1) sf[nt][3] = -CUDART_INF_F;
            }
        }

        float t0 = -CUDART_INF_F, t1 = -CUDART_INF_F;
        #pragma unroll
        for (int nt = 0; nt < 8; nt++) {
            t0 = fmaxf(t0, fmaxf(sf[nt][0], sf[nt][1]));
            t1 = fmaxf(t1, fmaxf(sf[nt][2], sf[nt][3]));
        }
        t0 = fmaxf(t0, __shfl_xor_sync(0xffffffffu, t0, 1));
        t0 = fmaxf(t0, __shfl_xor_sync(0xffffffffu, t0, 2));
        t1 = fmaxf(t1, __shfl_xor_sync(0xffffffffu, t1, 1));
        t1 = fmaxf(t1, __shfl_xor_sync(0xffffffffu, t1, 2));

        const float mn0 = fmaxf(m0, t0);
        const float mn1 = fmaxf(m1, t1);
        const float al0 = __expf(m0 - mn0);
        const float al1 = __expf(m1 - mn1);
        m0 = mn0; m1 = mn1;
        l0 *= al0; l1 *= al1;
        #pragma unroll
        for (int dt = 0; dt < 8; dt++) {
            of[dt][0] *= al0; of[dt][1] *= al0;
            of[dt][2] *= al1; of[dt][3] *= al1;
        }

        uint32_t pa[4][4];
        #pragma unroll
        for (int nt = 0; nt < 8; nt++) {
            const float p0 = __expf(sf[nt][0] - m0);
            const float p1 = __expf(sf[nt][1] - m0);
            const float p2 = __expf(sf[nt][2] - m1);
            const float p3 = __expf(sf[nt][3] - m1);
            l0 += p0 + p1;
            l1 += p2 + p3;
            const uint32_t lo = h2u(__floats2half2_rn(p0, p1));
            const uint32_t hi = h2u(__floats2half2_rn(p2, p3));
            const int kc  = nt >> 1;
            if ((nt & 1) == 0) { pa[kc][0] = lo; pa[kc][1] = hi; }
            else               { pa[kc][2] = lo; pa[kc][3] = hi; }
        }

        #pragma unroll
        for (int dt = 0; dt < 8; dt++) {
            const int dr = dt * 8 + g;
            #pragma unroll
            for (int kc = 0; kc < 4; kc++) {
                uint32_t b0 = *(const uint32_t*)&VsT[dr][kc * 16 + tig * 2];
                uint32_t b1 = *(const uint32_t*)&VsT[dr][kc * 16 + tig * 2 + 8];
                mma_f16(of[dt], pa[kc], b0, b1);
            }
        }
    }

    l0 += __shfl_xor_sync(0xffffffffu, l0, 1);
    l0 += __shfl_xor_sync(0xffffffffu, l0, 2);
    l1 += __shfl_xor_sync(0xffffffffu, l1, 1);
    l1 += __shfl_xor_sync(0xffffffffu, l1, 2);
    const float inv0 = 1.0f / l0;
    const float inv1 = 1.0f / l1;

    float* Ob = g_O + (size_t)bh * SEQ * HDIM;
    #pragma unroll
    for (int dt = 0; dt < 8; dt++) {
        const int col = dt * 8 + tig * 2;
        *(float2*)&Ob[(size_t)row0 * HDIM + col] =
            make_float2(of[dt][0] * inv0, of[dt][1] * inv0);
        *(float2*)&Ob[(size_t)row1 * HDIM + col] =
            make_float2(of[dt][2] * inv1, of[dt][3] * inv1);
    }
}

// ---------------------------------------------------------------------------
// Kernel 3: output projection, same structure as qkv_gemm; A gathered from
// g_O [B,H,T,D] via cp.async (16B chunks are contiguous within a head).
// ---------------------------------------------------------------------------
__global__ __launch_bounds__(256) void out_gemm(
    const float* __restrict__ W,    // [1024, 1024]
    const float* __restrict__ bias, // [1024]
    float* __restrict__ out)        // [8192, 1024]
{
    __shared__ float As[2][128][ASTR];
    __shared__ float Bs[2][16][PAD];

    const int tid = threadIdx.x;
    const int wid = tid >> 5;
    const int lane = tid & 31;
    const int g = lane >> 2;
    const int tig = lane & 3;
    const int warp_m = wid >> 1;
    const int warp_n = wid & 1;

    const int bm = blockIdx.y * 128;
    const int bn = blockIdx.x * 128;

    const int ar = tid >> 2;
    const int ac = (tid & 3) * 4;
    const int br = tid >> 5;
    const int bc = (tid & 31) * 4;

    const float* Bp0 = W + (size_t)br * CDIM + bn + bc;
    const float* Bp1 = W + (size_t)(br + 8) * CDIM + bn + bc;

    const int row0g = bm + ar;
    const int row1g = bm + ar + 64;
    const int bb0 = row0g >> 11, t0r = row0g & 2047;
    const int bb1 = row1g >> 11, t1r = row1g & 2047;

    float acc[2][8][4];
    #pragma unroll
    for (int mt = 0; mt < 2; mt++)
        #pragma unroll
        for (int nt = 0; nt < 8; nt++)
            #pragma unroll
            for (int i = 0; i < 4; i++) acc[mt][nt][i] = 0.f;

    auto issue_cp = [&](int buf, int k0) {
        const int k = k0 + ac;
        const int h = k >> 6;
        const int d = k & 63;
        cp16(&As[buf][ar][ac],
             &g_O[((bb0 * NHEAD + h) * SEQ + t0r) * HDIM + d]);
        cp16(&As[buf][ar + 64][ac],
             &g_O[((bb1 * NHEAD + h) * SEQ + t1r) * HDIM + d]);
        cp16(&Bs[buf][br][bc],     Bp0 + (size_t)k0 * CDIM);
        cp16(&Bs[buf][br + 8][bc], Bp1 + (size_t)k0 * CDIM);
        CP_COMMIT();
    };

    issue_cp(0, 0);
    CP_WAIT0();
    __syncthreads();

    const int am = warp_m * 32;
    const int an = warp_n * 64;

    int cur = 0;
    for (int k0 = 0; k0 < CDIM; k0 += 16) {
        const bool has_next = (k0 + 16) < CDIM;
        if (has_next) issue_cp(cur ^ 1, k0 + 16);

        #pragma unroll
        for (int kk = 0; kk < 16; kk += 8) {
            uint32_t Af[2][4], Bf[8][2];
            #pragma unroll
            for (int mt = 0; mt < 2; mt++) {
                const int m0 = am + mt * 16;
                Af[mt][0] = f2tf32(As[cur][m0 + g][kk + tig]);
                Af[mt][1] = f2tf32(As[cur][m0 + g + 8][kk + tig]);
                Af[mt][2] = f2tf32(As[cur][m0 + g][kk + tig + 4]);
                Af[mt][3] = f2tf32(As[cur][m0 + g + 8][kk + tig + 4]);
            }
            #pragma unroll
            for (int nt = 0; nt < 8; nt++) {
                const int n0 = an + nt * 8;
                Bf[nt][0] = f2tf32(Bs[cur][kk + tig][n0 + g]);
                Bf[nt][1] = f2tf32(Bs[cur][kk + tig + 4][n0 + g]);
            }
            #pragma unroll
            for (int mt = 0; mt < 2; mt++)
                #pragma unroll
                for (int nt = 0; nt < 8; nt++)
                    mma_tf32(acc[mt][nt], Af[mt], Bf[nt][0], Bf[nt][1]);
        }

        if (has_next) {
            CP_WAIT0();
            __syncthreads();
            cur ^= 1;
        }
    }

    #pragma unroll
    for (int mt = 0; mt < 2; mt++) {
        #pragma unroll
        for (int half = 0; half < 2; half++) {
            const int row = bm + am + mt * 16 + g + half * 8;
            #pragma unroll
            for (int nt = 0; nt < 8; nt++) {
                const int col = bn + an + nt * 8 + tig * 2;
                float v0 = acc[mt][nt][half * 2 + 0] + bias[col];
                float v1 = acc[mt][nt][half * 2 + 1] + bias[col + 1];
                *(float2*)&out[(size_t)row * CDIM + col] = make_float2(v0, v1);
            }
        }
    }
}

// ---------------------------------------------------------------------------
extern "C" void kernel_launch(void* const* d_in, const int* in_sizes, int n_in,
                              void* d_out, int out_size)
{
    const float* x     = (const float*)d_in[0];
    const float* W_qkv = (const float*)d_in[1];
    const float* b_qkv = (const float*)d_in[2];
    const float* W_out = (const float*)d_in[3];
    const float* b_out = (const float*)d_in[4];
    float* out = (float*)d_out;

    qkv_gemm<<<dim3(N3C / 128, (BATCH * SEQ) / 128), 256>>>(x, W_qkv, b_qkv);
    attn_kernel<<<dim3(SEQ / 128, BATCH * NHEAD), 256>>>();
    out_gemm<<<dim3(CDIM / 128, (BATCH * SEQ) / 128), 256>>>(W_out, b_out, out);
}

// round 11
// speedup vs baseline: 1.1442x; 1.0268x over previous
#include <cuda_runtime.h>
#include <cuda_bf16.h>
#include <cuda_fp16.h>
#include <math_constants.h>
#include <cstdint>
#include <cstring>

#define BATCH 4
#define SEQ   2048
#define CDIM  1024
#define NHEAD 16
#define HDIM  64
#define N3C   3072

__device__ float g_Q[BATCH * NHEAD * SEQ * HDIM];
__device__ float g_K[BATCH * NHEAD * SEQ * HDIM];
__device__ float g_V[BATCH * NHEAD * SEQ * HDIM];
__device__ float g_O[BATCH * NHEAD * SEQ * HDIM];
// tf32-pre-rounded copies (bit pattern = tf32 encoding, low 13 bits zero)
__device__ float g_Xr[BATCH * SEQ * CDIM];
__device__ float g_Wqr[CDIM * N3C];
__device__ float g_Wor[CDIM * CDIM];

// ---------------------------------------------------------------------------
// helpers
// ---------------------------------------------------------------------------
__device__ __forceinline__ uint32_t f2tf32(float f) {
    uint32_t r;
    asm("cvt.rna.tf32.f32 %0, %1;" : "=r"(r) : "f"(f));
    return r;
}

__device__ __forceinline__ float roundtf(float f) {
    return __uint_as_float(f2tf32(f));
}

__device__ __forceinline__ uint32_t h2u(__half2 h) {
    uint32_t r;
    memcpy(&r, &h, 4);
    return r;
}

__device__ __forceinline__ void cp16(void* smem, const void* gmem) {
    uint32_t s = (uint32_t)__cvta_generic_to_shared(smem);
    asm volatile("cp.async.cg.shared.global [%0], [%1], 16;"
                 :: "r"(s), "l"(gmem) : "memory");
}
#define CP_COMMIT() asm volatile("cp.async.commit_group;" ::: "memory")
#define CP_WAIT0()  asm volatile("cp.async.wait_group 0;" ::: "memory")

__device__ __forceinline__ void mma_tf32(float c[4],
                                         const uint32_t a[4],
                                         uint32_t b0, uint32_t b1) {
    asm volatile(
        "mma.sync.aligned.m16n8k8.row.col.f32.tf32.tf32.f32 "
        "{%0,%1,%2,%3}, {%4,%5,%6,%7}, {%8,%9}, {%0,%1,%2,%3};\n"
        : "+f"(c[0]), "+f"(c[1]), "+f"(c[2]), "+f"(c[3])
        : "r"(a[0]), "r"(a[1]), "r"(a[2]), "r"(a[3]),
          "r"(b0), "r"(b1));
}

__device__ __forceinline__ void mma_f16(float c[4],
                                        const uint32_t a[4],
                                        uint32_t b0, uint32_t b1) {
    asm volatile(
        "mma.sync.aligned.m16n8k16.row.col.f32.f16.f16.f32 "
        "{%0,%1,%2,%3}, {%4,%5,%6,%7}, {%8,%9}, {%0,%1,%2,%3};\n"
        : "+f"(c[0]), "+f"(c[1]), "+f"(c[2]), "+f"(c[3])
        : "r"(a[0]), "r"(a[1]), "r"(a[2]), "r"(a[3]),
          "r"(b0), "r"(b1));
}

#define PAD  136   // B smem row stride (floats): banks 8*tig+g bijective
#define ASTR 20    // A smem row stride (floats): bases 20g mod 32 all distinct

// ---------------------------------------------------------------------------
// Kernel 0: tf32 pre-rounding prepass (grid-stride float4)
// ---------------------------------------------------------------------------
__global__ __launch_bounds__(256) void round_kernel(
    const float* __restrict__ src, float* __restrict__ dst, int n4)
{
    for (int i = blockIdx.x * blockDim.x + threadIdx.x; i < n4;
         i += gridDim.x * blockDim.x) {
        float4 v = ((const float4*)src)[i];
        v.x = roundtf(v.x); v.y = roundtf(v.y);
        v.z = roundtf(v.z); v.w = roundtf(v.w);
        ((float4*)dst)[i] = v;
    }
}

// ---------------------------------------------------------------------------
// Kernel 1: QKV GEMM, tf32 mma, 128x128 CTA tile, BK=16, 256 threads,
// 8 warps (4Mx2N), 32x64 per warp. cp.async.cg staging of PRE-ROUNDED data:
// fragment loads are raw bit reinterpretation, zero CVTs in the hot loop.
// ---------------------------------------------------------------------------
__global__ __launch_bounds__(256) void qkv_gemm(
    const float* __restrict__ X,    // [8192, 1024]  pre-rounded
    const float* __restrict__ W,    // [1024, 3072]  pre-rounded
    const float* __restrict__ bias) // [3072]
{
    __shared__ float As[2][128][ASTR];   // [m][k] tf32-bit f32
    __shared__ float Bs[2][16][PAD];     // [k][n] tf32-bit f32

    const int tid = threadIdx.x;
    const int wid = tid >> 5;
    const int lane = tid & 31;
    const int g = lane >> 2;
    const int tig = lane & 3;
    const int warp_m = wid >> 1;
    const int warp_n = wid & 1;

    const int bm = blockIdx.y * 128;
    const int bn = blockIdx.x * 128;

    const int ar = tid >> 2;
    const int ac = (tid & 3) * 4;
    const int br = tid >> 5;
    const int bc = (tid & 31) * 4;

    const float* Ap0 = X + (size_t)(bm + ar) * CDIM + ac;
    const float* Ap1 = X + (size_t)(bm + ar + 64) * CDIM + ac;
    const float* Bp0 = W + (size_t)br * N3C + bn + bc;
    const float* Bp1 = W + (size_t)(br + 8) * N3C + bn + bc;

    float acc[2][8][4];
    #pragma unroll
    for (int mt = 0; mt < 2; mt++)
        #pragma unroll
        for (int nt = 0; nt < 8; nt++)
            #pragma unroll
            for (int i = 0; i < 4; i++) acc[mt][nt][i] = 0.f;

    auto issue_cp = [&](int buf, int k0) {
        cp16(&As[buf][ar][ac],      Ap0 + k0);
        cp16(&As[buf][ar + 64][ac], Ap1 + k0);
        cp16(&Bs[buf][br][bc],      Bp0 + (size_t)k0 * N3C);
        cp16(&Bs[buf][br + 8][bc],  Bp1 + (size_t)k0 * N3C);
        CP_COMMIT();
    };

    issue_cp(0, 0);
    CP_WAIT0();
    __syncthreads();

    const int am = warp_m * 32;
    const int an = warp_n * 64;

    int cur = 0;
    for (int k0 = 0; k0 < CDIM; k0 += 16) {
        const bool has_next = (k0 + 16) < CDIM;
        if (has_next) issue_cp(cur ^ 1, k0 + 16);

        #pragma unroll
        for (int kk = 0; kk < 16; kk += 8) {
            uint32_t Af[2][4], Bf[8][2];
            #pragma unroll
            for (int mt = 0; mt < 2; mt++) {
                const int m0 = am + mt * 16;
                Af[mt][0] = __float_as_uint(As[cur][m0 + g][kk + tig]);
                Af[mt][1] = __float_as_uint(As[cur][m0 + g + 8][kk + tig]);
                Af[mt][2] = __float_as_uint(As[cur][m0 + g][kk + tig + 4]);
                Af[mt][3] = __float_as_uint(As[cur][m0 + g + 8][kk + tig + 4]);
            }
            #pragma unroll
            for (int nt = 0; nt < 8; nt++) {
                const int n0 = an + nt * 8;
                Bf[nt][0] = __float_as_uint(Bs[cur][kk + tig][n0 + g]);
                Bf[nt][1] = __float_as_uint(Bs[cur][kk + tig + 4][n0 + g]);
            }
            #pragma unroll
            for (int mt = 0; mt < 2; mt++)
                #pragma unroll
                for (int nt = 0; nt < 8; nt++)
                    mma_tf32(acc[mt][nt], Af[mt], Bf[nt][0], Bf[nt][1]);
        }

        if (has_next) {
            CP_WAIT0();
            __syncthreads();
            cur ^= 1;
        }
    }

    // Epilogue: Q scaled then tf32-rounded; K tf32-rounded (consumers read
    // raw bits); V plain fp32 (attention converts to f16 at staging).
    #pragma unroll
    for (int mt = 0; mt < 2; mt++) {
        #pragma unroll
        for (int half = 0; half < 2; half++) {
            const int row = bm + am + mt * 16 + g + half * 8;
            const int bb = row >> 11;
            const int t  = row & 2047;
            #pragma unroll
            for (int nt = 0; nt < 8; nt++) {
                const int col = bn + an + nt * 8 + tig * 2;
                float v0 = acc[mt][nt][half * 2 + 0] + bias[col];
                float v1 = acc[mt][nt][half * 2 + 1] + bias[col + 1];
                const int part = col >> 10;      // 0=Q 1=K 2=V
                const int cc = col & 1023;
                const int h = cc >> 6;
                const int d = cc & 63;
                if (part == 0) {
                    v0 = roundtf(v0 * 0.125f);
                    v1 = roundtf(v1 * 0.125f);
                } else if (part == 1) {
                    v0 = roundtf(v0);
                    v1 = roundtf(v1);
                }
                float* dst = (part == 0) ? g_Q : ((part == 1) ? g_K : g_V);
                const int idx = ((bb * NHEAD + h) * SEQ + t) * HDIM + d;
                *(float2*)&dst[idx] = make_float2(v0, v1);
            }
        }
    }
}

// ---------------------------------------------------------------------------
// Kernel 2: tensor-core causal flash attention. Q/K arrive pre-rounded
// (raw-bit loads); V converted to f16 at staging; O stored tf32-rounded
// for the cvt-free out_gemm A path.
// ---------------------------------------------------------------------------
#define KSTRIDE 68   // Ks row stride (floats)
#define VSTRIDE 72   // VsT row stride (halves)

__global__ __launch_bounds__(256) void attn_kernel()
{
    const int bh  = blockIdx.y;
    const int qt  = (SEQ / 128 - 1) - blockIdx.x;
    const int tid = threadIdx.x;
    const int wid = tid >> 5;
    const int lane = tid & 31;
    const int g   = lane >> 2;
    const int tig = lane & 3;

    const int qbase = qt * 128;
    const int wbase = qbase + wid * 16;
    const int row0  = wbase + g;
    const int row1  = row0 + 8;

    __shared__ uint32_t Ks[64][KSTRIDE];
    __shared__ __half   VsT[64][VSTRIDE];

    const float* Qb = g_Q + (size_t)bh * SEQ * HDIM;
    const float* Kb = g_K + (size_t)bh * SEQ * HDIM;
    const float* Vb = g_V + (size_t)bh * SEQ * HDIM;

    uint32_t qf[8][4];
    #pragma unroll
    for (int kt8 = 0; kt8 < 8; kt8++) {
        qf[kt8][0] = __float_as_uint(Qb[(size_t)row0 * HDIM + kt8 * 8 + tig]);
        qf[kt8][1] = __float_as_uint(Qb[(size_t)row1 * HDIM + kt8 * 8 + tig]);
        qf[kt8][2] = __float_as_uint(Qb[(size_t)row0 * HDIM + kt8 * 8 + tig + 4]);
        qf[kt8][3] = __float_as_uint(Qb[(size_t)row1 * HDIM + kt8 * 8 + tig + 4]);
    }

    float of[8][4];
    #pragma unroll
    for (int dt = 0; dt < 8; dt++)
        #pragma unroll
        for (int i = 0; i < 4; i++) of[dt][i] = 0.f;

    float m0 = -CUDART_INF_F, m1 = -CUDART_INF_F;
    float l0 = 0.f, l1 = 0.f;

    const int ktmax = (qbase + 127) >> 6;

    for (int kt = 0; kt <= ktmax; kt++) {
        __syncthreads();
        #pragma unroll
        for (int i = 0; i < 4; i++) {
            const int idx = tid + i * 256;
            const int key = idx >> 4;
            const int c4  = (idx & 15) * 4;
            const size_t gidx = (size_t)(kt * 64 + key) * HDIM + c4;
            float4 kv = *(const float4*)(Kb + gidx);   // pre-rounded: raw copy
            uint32_t* kd = &Ks[key][c4];
            kd[0] = __float_as_uint(kv.x); kd[1] = __float_as_uint(kv.y);
            kd[2] = __float_as_uint(kv.z); kd[3] = __float_as_uint(kv.w);
            float4 vv = *(const float4*)(Vb + gidx);
            VsT[c4 + 0][key] = __float2half(vv.x);
            VsT[c4 + 1][key] = __float2half(vv.y);
            VsT[c4 + 2][key] = __float2half(vv.z);
            VsT[c4 + 3][key] = __float2half(vv.w);
        }
        __syncthreads();

        if (kt * 64 > wbase + 15) continue;

        float sf[8][4];
        #pragma unroll
        for (int nt = 0; nt < 8; nt++) {
            sf[nt][0] = sf[nt][1] = sf[nt][2] = sf[nt][3] = 0.f;
            const int kr = nt * 8 + g;
            #pragma unroll
            for (int kt8 = 0; kt8 < 8; kt8++) {
                uint32_t b0 = Ks[kr][kt8 * 8 + tig];
                uint32_t b1 = Ks[kr][kt8 * 8 + tig + 4];
                mma_tf32(sf[nt], qf[kt8], b0, b1);
            }
        }

        const int colbase = kt * 64;
        if (colbase + 63 > wbase) {
            #pragma unroll
            for (int nt = 0; nt < 8; nt++) {
                const int c = colbase + nt * 8 + tig * 2;
                if (c     > row0) sf[nt][0] = -CUDART_INF_F;
                if (c + 1 > row0) sf[nt][1] = -CUDART_INF_F;
                if (c     > row1) sf[nt][2] = -CUDART_INF_F;
                if (c + 1 > row1) sf[nt][3] = -CUDART_INF_F;
            }
        }

        float t0 = -CUDART_INF_F, t1 = -CUDART_INF_F;
        #pragma unroll
        for (int nt = 0; nt < 8; nt++) {
            t0 = fmaxf(t0, fmaxf(sf[nt][0], sf[nt][1]));
            t1 = fmaxf(t1, fmaxf(sf[nt][2], sf[nt][3]));
        }
        t0 = fmaxf(t0, __shfl_xor_sync(0xffffffffu, t0, 1));
        t0 = fmaxf(t0, __shfl_xor_sync(0xffffffffu, t0, 2));
        t1 = fmaxf(t1, __shfl_xor_sync(0xffffffffu, t1, 1));
        t1 = fmaxf(t1, __shfl_xor_sync(0xffffffffu, t1, 2));

        const float mn0 = fmaxf(m0, t0);
        const float mn1 = fmaxf(m1, t1);
        const float al0 = __expf(m0 - mn0);
        const float al1 = __expf(m1 - mn1);
        m0 = mn0; m1 = mn1;
        l0 *= al0; l1 *= al1;
        #pragma unroll
        for (int dt = 0; dt < 8; dt++) {
            of[dt][0] *= al0; of[dt][1] *= al0;
            of[dt][2] *= al1; of[dt][3] *= al1;
        }

        uint32_t pa[4][4];
        #pragma unroll
        for (int nt = 0; nt < 8; nt++) {
            const float p0 = __expf(sf[nt][0] - m0);
            const float p1 = __expf(sf[nt][1] - m0);
            const float p2 = __expf(sf[nt][2] - m1);
            const float p3 = __expf(sf[nt][3] - m1);
            l0 += p0 + p1;
            l1 += p2 + p3;
            const uint32_t lo = h2u(__floats2half2_rn(p0, p1));
            const uint32_t hi = h2u(__floats2half2_rn(p2, p3));
            const int kc  = nt >> 1;
            if ((nt & 1) == 0) { pa[kc][0] = lo; pa[kc][1] = hi; }
            else               { pa[kc][2] = lo; pa[kc][3] = hi; }
        }

        #pragma unroll
        for (int dt = 0; dt < 8; dt++) {
            const int dr = dt * 8 + g;
            #pragma unroll
            for (int kc = 0; kc < 4; kc++) {
                uint32_t b0 = *(const uint32_t*)&VsT[dr][kc * 16 + tig * 2];
                uint32_t b1 = *(const uint32_t*)&VsT[dr][kc * 16 + tig * 2 + 8];
                mma_f16(of[dt], pa[kc], b0, b1);
            }
        }
    }

    l0 += __shfl_xor_sync(0xffffffffu, l0, 1);
    l0 += __shfl_xor_sync(0xffffffffu, l0, 2);
    l1 += __shfl_xor_sync(0xffffffffu, l1, 1);
    l1 += __shfl_xor_sync(0xffffffffu, l1, 2);
    const float inv0 = 1.0f / l0;
    const float inv1 = 1.0f / l1;

    float* Ob = g_O + (size_t)bh * SEQ * HDIM;
    #pragma unroll
    for (int dt = 0; dt < 8; dt++) {
        const int col = dt * 8 + tig * 2;
        *(float2*)&Ob[(size_t)row0 * HDIM + col] =
            make_float2(roundtf(of[dt][0] * inv0), roundtf(of[dt][1] * inv0));
        *(float2*)&Ob[(size_t)row1 * HDIM + col] =
            make_float2(roundtf(of[dt][2] * inv1), roundtf(of[dt][3] * inv1));
    }
}

// ---------------------------------------------------------------------------
// Kernel 3: output projection; A = g_O (pre-rounded), B = g_Wor (pre-rounded).
// Zero CVTs in the hot loop.
// ---------------------------------------------------------------------------
__global__ __launch_bounds__(256) void out_gemm(
    const float* __restrict__ W,    // [1024, 1024] pre-rounded
    const float* __restrict__ bias, // [1024]
    float* __restrict__ out)        // [8192, 1024]
{
    __shared__ float As[2][128][ASTR];
    __shared__ float Bs[2][16][PAD];

    const int tid = threadIdx.x;
    const int wid = tid >> 5;
    const int lane = tid & 31;
    const int g = lane >> 2;
    const int tig = lane & 3;
    const int warp_m = wid >> 1;
    const int warp_n = wid & 1;

    const int bm = blockIdx.y * 128;
    const int bn = blockIdx.x * 128;

    const int ar = tid >> 2;
    const int ac = (tid & 3) * 4;
    const int br = tid >> 5;
    const int bc = (tid & 31) * 4;

    const float* Bp0 = W + (size_t)br * CDIM + bn + bc;
    const float* Bp1 = W + (size_t)(br + 8) * CDIM + bn + bc;

    const int row0g = bm + ar;
    const int row1g = bm + ar + 64;
    const int bb0 = row0g >> 11, t0r = row0g & 2047;
    const int bb1 = row1g >> 11, t1r = row1g & 2047;

    float acc[2][8][4];
    #pragma unroll
    for (int mt = 0; mt < 2; mt++)
        #pragma unroll
        for (int nt = 0; nt < 8; nt++)
            #pragma unroll
            for (int i = 0; i < 4; i++) acc[mt][nt][i] = 0.f;

    auto issue_cp = [&](int buf, int k0) {
        const int k = k0 + ac;
        const int h = k >> 6;
        const int d = k & 63;
        cp16(&As[buf][ar][ac],
             &g_O[((bb0 * NHEAD + h) * SEQ + t0r) * HDIM + d]);
        cp16(&As[buf][ar + 64][ac],
             &g_O[((bb1 * NHEAD + h) * SEQ + t1r) * HDIM + d]);
        cp16(&Bs[buf][br][bc],     Bp0 + (size_t)k0 * CDIM);
        cp16(&Bs[buf][br + 8][bc], Bp1 + (size_t)k0 * CDIM);
        CP_COMMIT();
    };

    issue_cp(0, 0);
    CP_WAIT0();
    __syncthreads();

    const int am = warp_m * 32;
    const int an = warp_n * 64;

    int cur = 0;
    for (int k0 = 0; k0 < CDIM; k0 += 16) {
        const bool has_next = (k0 + 16) < CDIM;
        if (has_next) issue_cp(cur ^ 1, k0 + 16);

        #pragma unroll
        for (int kk = 0; kk < 16; kk += 8) {
            uint32_t Af[2][4], Bf[8][2];
            #pragma unroll
            for (int mt = 0; mt < 2; mt++) {
                const int m0 = am + mt * 16;
                Af[mt][0] = __float_as_uint(As[cur][m0 + g][kk + tig]);
                Af[mt][1] = __float_as_uint(As[cur][m0 + g + 8][kk + tig]);
                Af[mt][2] = __float_as_uint(As[cur][m0 + g][kk + tig + 4]);
                Af[mt][3] = __float_as_uint(As[cur][m0 + g + 8][kk + tig + 4]);
            }
            #pragma unroll
            for (int nt = 0; nt < 8; nt++) {
                const int n0 = an + nt * 8;
                Bf[nt][0] = __float_as_uint(Bs[cur][kk + tig][n0 + g]);
                Bf[nt][1] = __float_as_uint(Bs[cur][kk + tig + 4][n0 + g]);
            }
            #pragma unroll
            for (int mt = 0; mt < 2; mt++)
                #pragma unroll
                for (int nt = 0; nt < 8; nt++)
                    mma_tf32(acc[mt][nt], Af[mt], Bf[nt][0], Bf[nt][1]);
        }

        if (has_next) {
            CP_WAIT0();
            __syncthreads();
            cur ^= 1;
        }
    }

    #pragma unroll
    for (int mt = 0; mt < 2; mt++) {
        #pragma unroll
        for (int half = 0; half < 2; half++) {
            const int row = bm + am + mt * 16 + g + half * 8;
            #pragma unroll
            for (int nt = 0; nt < 8; nt++) {
                const int col = bn + an + nt * 8 + tig * 2;
                float v0 = acc[mt][nt][half * 2 + 0] + bias[col];
                float v1 = acc[mt][nt][half * 2 + 1] + bias[col + 1];
                *(float2*)&out[(size_t)row * CDIM + col] = make_float2(v0, v1);
            }
        }
    }
}

// ---------------------------------------------------------------------------
extern "C" void kernel_launch(void* const* d_in, const int* in_sizes, int n_in,
                              void* d_out, int out_size)
{
    const float* x     = (const float*)d_in[0];
    const float* W_qkv = (const float*)d_in[1];
    const float* b_qkv = (const float*)d_in[2];
    const float* W_out = (const float*)d_in[3];
    const float* b_out = (const float*)d_in[4];
    float* out = (float*)d_out;

    float *d_Xr, *d_Wqr, *d_Wor;
    cudaGetSymbolAddress((void**)&d_Xr,  g_Xr);
    cudaGetSymbolAddress((void**)&d_Wqr, g_Wqr);
    cudaGetSymbolAddress((void**)&d_Wor, g_Wor);

    // 0) tf32 pre-rounding prepass
    round_kernel<<<2048, 256>>>(x,     d_Xr,  (BATCH * SEQ * CDIM) / 4);
    round_kernel<<<2048, 256>>>(W_qkv, d_Wqr, (CDIM * N3C) / 4);
    round_kernel<<<1024, 256>>>(W_out, d_Wor, (CDIM * CDIM) / 4);

    // 1) QKV projection (cvt-free hot loop)
    qkv_gemm<<<dim3(N3C / 128, (BATCH * SEQ) / 128), 256>>>(d_Xr, d_Wqr, b_qkv);

    // 2) causal flash attention
    attn_kernel<<<dim3(SEQ / 128, BATCH * NHEAD), 256>>>();

    // 3) output projection (cvt-free hot loop)
    out_gemm<<<dim3(CDIM / 128, (BATCH * SEQ) / 128), 256>>>(d_Wor, b_out, out);
}

// round 15
// speedup vs baseline: 1.3281x; 1.1608x over previous
#include <cuda_runtime.h>
#include <cuda_bf16.h>
#include <cuda_fp16.h>
#include <math_constants.h>
#include <cstdint>
#include <cstring>

#define BATCH 4
#define SEQ   2048
#define CDIM  1024
#define NHEAD 16
#define HDIM  64
#define N3C   3072

__device__ float  g_Q[BATCH * NHEAD * SEQ * HDIM];
__device__ float  g_K[BATCH * NHEAD * SEQ * HDIM];
__device__ __half g_Vh[BATCH * NHEAD * HDIM * SEQ];   // [B,H,D,T] f16
__device__ float  g_O[BATCH * NHEAD * SEQ * HDIM];
// tf32-pre-rounded copies (bit pattern = tf32 encoding, low 13 bits zero)
__device__ float g_Xr[BATCH * SEQ * CDIM];
__device__ float g_Wqr[CDIM * N3C];
__device__ float g_Wor[CDIM * CDIM];

// ---------------------------------------------------------------------------
// helpers
// ---------------------------------------------------------------------------
__device__ __forceinline__ uint32_t f2tf32(float f) {
    uint32_t r;
    asm("cvt.rna.tf32.f32 %0, %1;" : "=r"(r) : "f"(f));
    return r;
}

__device__ __forceinline__ float roundtf(float f) {
    return __uint_as_float(f2tf32(f));
}

__device__ __forceinline__ uint32_t h2u(__half2 h) {
    uint32_t r;
    memcpy(&r, &h, 4);
    return r;
}

__device__ __forceinline__ void cp16(void* smem, const void* gmem) {
    uint32_t s = (uint32_t)__cvta_generic_to_shared(smem);
    asm volatile("cp.async.cg.shared.global [%0], [%1], 16;"
                 :: "r"(s), "l"(gmem) : "memory");
}
#define CP_COMMIT() asm volatile("cp.async.commit_group;" ::: "memory")
#define CP_WAIT0()  asm volatile("cp.async.wait_group 0;" ::: "memory")
#define CP_WAIT1()  asm volatile("cp.async.wait_group 1;" ::: "memory")

__device__ __forceinline__ void mma_tf32(float c[4],
                                         const uint32_t a[4],
                                         uint32_t b0, uint32_t b1) {
    asm volatile(
        "mma.sync.aligned.m16n8k8.row.col.f32.tf32.tf32.f32 "
        "{%0,%1,%2,%3}, {%4,%5,%6,%7}, {%8,%9}, {%0,%1,%2,%3};\n"
        : "+f"(c[0]), "+f"(c[1]), "+f"(c[2]), "+f"(c[3])
        : "r"(a[0]), "r"(a[1]), "r"(a[2]), "r"(a[3]),
          "r"(b0), "r"(b1));
}

__device__ __forceinline__ void mma_f16(float c[4],
                                        const uint32_t a[4],
                                        uint32_t b0, uint32_t b1) {
    asm volatile(
        "mma.sync.aligned.m16n8k16.row.col.f32.f16.f16.f32 "
        "{%0,%1,%2,%3}, {%4,%5,%6,%7}, {%8,%9}, {%0,%1,%2,%3};\n"
        : "+f"(c[0]), "+f"(c[1]), "+f"(c[2]), "+f"(c[3])
        : "r"(a[0]), "r"(a[1]), "r"(a[2]), "r"(a[3]),
          "r"(b0), "r"(b1));
}

#define PAD  136   // B smem row stride (floats): banks 8*tig+g bijective
#define ASTR 20    // A smem row stride (floats): bases 20g mod 32 all distinct

// ---------------------------------------------------------------------------
// Kernel 0: tf32 pre-rounding prepass (grid-stride float4)
// ---------------------------------------------------------------------------
__global__ __launch_bounds__(256) void round_kernel(
    const float* __restrict__ src, float* __restrict__ dst, int n4)
{
    for (int i = blockIdx.x * blockDim.x + threadIdx.x; i < n4;
         i += gridDim.x * blockDim.x) {
        float4 v = ((const float4*)src)[i];
        v.x = roundtf(v.x); v.y = roundtf(v.y);
        v.z = roundtf(v.z); v.w = roundtf(v.w);
        ((float4*)dst)[i] = v;
    }
}

// ---------------------------------------------------------------------------
// Kernel 1: QKV GEMM, tf32 mma, 128x128 CTA tile, BK=16, 256 threads,
// 8 warps (4Mx2N), 32x64 per warp. cp.async staging of pre-rounded data.
// minBlocksPerSM=3 to lift occupancy (regs capped at 85).
// ---------------------------------------------------------------------------
__global__ __launch_bounds__(256, 3) void qkv_gemm(
    const float* __restrict__ X,    // [8192, 1024]  pre-rounded
    const float* __restrict__ W,    // [1024, 3072]  pre-rounded
    const float* __restrict__ bias) // [3072]
{
    __shared__ float As[2][128][ASTR];   // [m][k] tf32-bit f32
    __shared__ float Bs[2][16][PAD];     // [k][n] tf32-bit f32

    const int tid = threadIdx.x;
    const int wid = tid >> 5;
    const int lane = tid & 31;
    const int g = lane >> 2;
    const int tig = lane & 3;
    const int warp_m = wid >> 1;
    const int warp_n = wid & 1;

    const int bm = blockIdx.y * 128;
    const int bn = blockIdx.x * 128;

    const int ar = tid >> 2;
    const int ac = (tid & 3) * 4;
    const int br = tid >> 5;
    const int bc = (tid & 31) * 4;

    const float* Ap0 = X + (size_t)(bm + ar) * CDIM + ac;
    const float* Ap1 = X + (size_t)(bm + ar + 64) * CDIM + ac;
    const float* Bp0 = W + (size_t)br * N3C + bn + bc;
    const float* Bp1 = W + (size_t)(br + 8) * N3C + bn + bc;

    float acc[2][8][4];
    #pragma unroll
    for (int mt = 0; mt < 2; mt++)
        #pragma unroll
        for (int nt = 0; nt < 8; nt++)
            #pragma unroll
            for (int i = 0; i < 4; i++) acc[mt][nt][i] = 0.f;

    auto issue_cp = [&](int buf, int k0) {
        cp16(&As[buf][ar][ac],      Ap0 + k0);
        cp16(&As[buf][ar + 64][ac], Ap1 + k0);
        cp16(&Bs[buf][br][bc],      Bp0 + (size_t)k0 * N3C);
        cp16(&Bs[buf][br + 8][bc],  Bp1 + (size_t)k0 * N3C);
        CP_COMMIT();
    };

    issue_cp(0, 0);
    CP_WAIT0();
    __syncthreads();

    const int am = warp_m * 32;
    const int an = warp_n * 64;

    int cur = 0;
    for (int k0 = 0; k0 < CDIM; k0 += 16) {
        const bool has_next = (k0 + 16) < CDIM;
        if (has_next) issue_cp(cur ^ 1, k0 + 16);

        #pragma unroll
        for (int kk = 0; kk < 16; kk += 8) {
            uint32_t Af[2][4], Bf[8][2];
            #pragma unroll
            for (int mt = 0; mt < 2; mt++) {
                const int m0 = am + mt * 16;
                Af[mt][0] = __float_as_uint(As[cur][m0 + g][kk + tig]);
                Af[mt][1] = __float_as_uint(As[cur][m0 + g + 8][kk + tig]);
                Af[mt][2] = __float_as_uint(As[cur][m0 + g][kk + tig + 4]);
                Af[mt][3] = __float_as_uint(As[cur][m0 + g + 8][kk + tig + 4]);
            }
            #pragma unroll
            for (int nt = 0; nt < 8; nt++) {
                const int n0 = an + nt * 8;
                Bf[nt][0] = __float_as_uint(Bs[cur][kk + tig][n0 + g]);
                Bf[nt][1] = __float_as_uint(Bs[cur][kk + tig + 4][n0 + g]);
            }
            #pragma unroll
            for (int mt = 0; mt < 2; mt++)
                #pragma unroll
                for (int nt = 0; nt < 8; nt++)
                    mma_tf32(acc[mt][nt], Af[mt], Bf[nt][0], Bf[nt][1]);
        }

        if (has_next) {
            CP_WAIT0();
            __syncthreads();
            cur ^= 1;
        }
    }

    // Epilogue: Q scaled+rounded; K rounded; V -> f16 in [B,H,D,T].
    #pragma unroll
    for (int mt = 0; mt < 2; mt++) {
        #pragma unroll
        for (int half = 0; half < 2; half++) {
            const int row = bm + am + mt * 16 + g + half * 8;
            const int bb = row >> 11;
            const int t  = row & 2047;
            #pragma unroll
            for (int nt = 0; nt < 8; nt++) {
                const int col = bn + an + nt * 8 + tig * 2;
                float v0 = acc[mt][nt][half * 2 + 0] + bias[col];
                float v1 = acc[mt][nt][half * 2 + 1] + bias[col + 1];
                const int part = col >> 10;      // 0=Q 1=K 2=V
                const int cc = col & 1023;
                const int h = cc >> 6;
                const int d = cc & 63;
                if (part == 2) {
                    __half* vd = g_Vh +
                        ((size_t)(bb * NHEAD + h) * HDIM + d) * SEQ + t;
                    vd[0]   = __float2half(v0);
                    vd[SEQ] = __float2half(v1);
                } else {
                    if (part == 0) {
                        v0 = roundtf(v0 * 0.125f);
                        v1 = roundtf(v1 * 0.125f);
                    } else {
                        v0 = roundtf(v0);
                        v1 = roundtf(v1);
                    }
                    float* dst = (part == 0) ? g_Q : g_K;
                    const int idx = ((bb * NHEAD + h) * SEQ + t) * HDIM + d;
                    *(float2*)&dst[idx] = make_float2(v0, v1);
                }
            }
        }
    }
}

// ---------------------------------------------------------------------------
// Kernel 2: tensor-core causal flash attention, cp.async double-buffered
// K/V staging (K raw pre-rounded f32, V raw f16 dim-major).
// ---------------------------------------------------------------------------
#define KSTRIDE 68                     // floats per key row (272B)
#define VSTRIDE 72                     // halves per dim row (144B)
#define KS_U32  (64 * KSTRIDE)         // 4352 u32 per buffer
#define VS_H    (64 * VSTRIDE)         // 4608 halves per buffer
#define ATTN_SMEM (2 * KS_U32 * 4 + 2 * VS_H * 2)   // 53248 B

__global__ __launch_bounds__(256) void attn_kernel()
{
    extern __shared__ uint32_t dynsmem[];
    uint32_t* KsB = dynsmem;                              // 2 buffers
    __half*  VsB = (__half*)(dynsmem + 2 * KS_U32);       // 2 buffers

    const int bh  = blockIdx.y;
    const int qt  = (SEQ / 128 - 1) - blockIdx.x;
    const int tid = threadIdx.x;
    const int wid = tid >> 5;
    const int lane = tid & 31;
    const int g   = lane >> 2;
    const int tig = lane & 3;

    const int qbase = qt * 128;
    const int wbase = qbase + wid * 16;
    const int row0  = wbase + g;
    const int row1  = row0 + 8;

    const float*  Qb = g_Q + (size_t)bh * SEQ * HDIM;
    const float*  Kb = g_K + (size_t)bh * SEQ * HDIM;
    const __half* Vb = g_Vh + (size_t)bh * HDIM * SEQ;

    uint32_t qf[8][4];
    #pragma unroll
    for (int kt8 = 0; kt8 < 8; kt8++) {
        qf[kt8][0] = __float_as_uint(Qb[(size_t)row0 * HDIM + kt8 * 8 + tig]);
        qf[kt8][1] = __float_as_uint(Qb[(size_t)row1 * HDIM + kt8 * 8 + tig]);
        qf[kt8][2] = __float_as_uint(Qb[(size_t)row0 * HDIM + kt8 * 8 + tig + 4]);
        qf[kt8][3] = __float_as_uint(Qb[(size_t)row1 * HDIM + kt8 * 8 + tig + 4]);
    }

    float of[8][4];
    #pragma unroll
    for (int dt = 0; dt < 8; dt++)
        #pragma unroll
        for (int i = 0; i < 4; i++) of[dt][i] = 0.f;

    float m0 = -CUDART_INF_F, m1 = -CUDART_INF_F;
    float l0 = 0.f, l1 = 0.f;

    const int ktmax = (qbase + 127) >> 6;

    // stage one 64-key tile into buffer buf (6 cp16 per thread, 1 group)
    auto stage_tile = [&](int buf, int kt) {
        uint32_t* Kd = KsB + buf * KS_U32;
        __half*   Vd = VsB + buf * VS_H;
        #pragma unroll
        for (int i = 0; i < 4; i++) {
            const int c = tid + i * 256;           // 0..1023
            const int key = c >> 4;
            const int off = (c & 15) * 4;
            cp16(Kd + key * KSTRIDE + off,
                 Kb + (size_t)(kt * 64 + key) * HDIM + off);
        }
        #pragma unroll
        for (int i = 0; i < 2; i++) {
            const int c = tid + i * 256;           // 0..511
            const int dim = c >> 3;
            const int ko  = (c & 7) * 8;
            cp16(Vd + dim * VSTRIDE + ko,
                 Vb + (size_t)dim * SEQ + kt * 64 + ko);
        }
        CP_COMMIT();
    };

    stage_tile(0, 0);

    int cur = 0;
    for (int kt = 0; kt <= ktmax; kt++) {
        const bool has_next = kt < ktmax;
        if (has_next) stage_tile(cur ^ 1, kt + 1);
        if (has_next) { CP_WAIT1(); } else { CP_WAIT0(); }
        __syncthreads();

        if (kt * 64 <= wbase + 15) {   // not fully masked for this warp
            const uint32_t* Kd = KsB + cur * KS_U32;
            const __half*   Vd = VsB + cur * VS_H;

            // ---- S = Q K^T ----
            float sf[8][4];
            #pragma unroll
            for (int nt = 0; nt < 8; nt++) {
                sf[nt][0] = sf[nt][1] = sf[nt][2] = sf[nt][3] = 0.f;
                const int kr = nt * 8 + g;
                #pragma unroll
                for (int kt8 = 0; kt8 < 8; kt8++) {
                    uint32_t b0 = Kd[kr * KSTRIDE + kt8 * 8 + tig];
                    uint32_t b1 = Kd[kr * KSTRIDE + kt8 * 8 + tig + 4];
                    mma_tf32(sf[nt], qf[kt8], b0, b1);
                }
            }

            // ---- causal mask (diagonal tiles) ----
            const int colbase = kt * 64;
            if (colbase + 63 > wbase) {
                #pragma unroll
                for (int nt = 0; nt < 8; nt++) {
                    const int c = colbase + nt * 8 + tig * 2;
                    if (c     > row0) sf[nt][0] = -CUDART_INF_F;
                    if (c + 1 > row0) sf[nt][1] = -CUDART_INF_F;
                    if (c     > row1) sf[nt][2] = -CUDART_INF_F;
                    if (c + 1 > row1) sf[nt][3] = -CUDART_INF_F;
                }
            }

            // ---- online softmax ----
            float t0 = -CUDART_INF_F, t1 = -CUDART_INF_F;
            #pragma unroll
            for (int nt = 0; nt < 8; nt++) {
                t0 = fmaxf(t0, fmaxf(sf[nt][0], sf[nt][1]));
                t1 = fmaxf(t1, fmaxf(sf[nt][2], sf[nt][3]));
            }
            t0 = fmaxf(t0, __shfl_xor_sync(0xffffffffu, t0, 1));
            t0 = fmaxf(t0, __shfl_xor_sync(0xffffffffu, t0, 2));
            t1 = fmaxf(t1, __shfl_xor_sync(0xffffffffu, t1, 1));
            t1 = fmaxf(t1, __shfl_xor_sync(0xffffffffu, t1, 2));

            const float mn0 = fmaxf(m0, t0);
            const float mn1 = fmaxf(m1, t1);
            const float al0 = __expf(m0 - mn0);
            const float al1 = __expf(m1 - mn1);
            m0 = mn0; m1 = mn1;
            l0 *= al0; l1 *= al1;
            #pragma unroll
            for (int dt = 0; dt < 8; dt++) {
                of[dt][0] *= al0; of[dt][1] *= al0;
                of[dt][2] *= al1; of[dt][3] *= al1;
            }

            uint32_t pa[4][4];
            #pragma unroll
            for (int nt = 0; nt < 8; nt++) {
                const float p0 = __expf(sf[nt][0] - m0);
                const float p1 = __expf(sf[nt][1] - m0);
                const float p2 = __expf(sf[nt][2] - m1);
                const float p3 = __expf(sf[nt][3] - m1);
                l0 += p0 + p1;
                l1 += p2 + p3;
                const uint32_t lo = h2u(__floats2half2_rn(p0, p1));
                const uint32_t hi = h2u(__floats2half2_rn(p2, p3));
                const int kc  = nt >> 1;
                if ((nt & 1) == 0) { pa[kc][0] = lo; pa[kc][1] = hi; }
                else               { pa[kc][2] = lo; pa[kc][3] = hi; }
            }

            // ---- O += P V ----
            #pragma unroll
            for (int dt = 0; dt < 8; dt++) {
                const int dr = dt * 8 + g;
                #pragma unroll
                for (int kc = 0; kc < 4; kc++) {
                    uint32_t b0 = *(const uint32_t*)&Vd[dr * VSTRIDE + kc * 16 + tig * 2];
                    uint32_t b1 = *(const uint32_t*)&Vd[dr * VSTRIDE + kc * 16 + tig * 2 + 8];
                    mma_f16(of[dt], pa[kc], b0, b1);
                }
            }
        }

        __syncthreads();   // all reads of cur done before it is re-staged
        cur ^= 1;
    }

    l0 += __shfl_xor_sync(0xffffffffu, l0, 1);
    l0 += __shfl_xor_sync(0xffffffffu, l0, 2);
    l1 += __shfl_xor_sync(0xffffffffu, l1, 1);
    l1 += __shfl_xor_sync(0xffffffffu, l1, 2);
    const float inv0 = 1.0f / l0;
    const float inv1 = 1.0f / l1;

    float* Ob = g_O + (size_t)bh * SEQ * HDIM;
    #pragma unroll
    for (int dt = 0; dt < 8; dt++) {
        const int col = dt * 8 + tig * 2;
        *(float2*)&Ob[(size_t)row0 * HDIM + col] =
            make_float2(roundtf(of[dt][0] * inv0), roundtf(of[dt][1] * inv0));
        *(float2*)&Ob[(size_t)row1 * HDIM + col] =
            make_float2(roundtf(of[dt][2] * inv1), roundtf(of[dt][3] * inv1));
    }
}

// ---------------------------------------------------------------------------
// Kernel 3: output projection; A = g_O (pre-rounded), B = g_Wor (pre-rounded).
// minBlocksPerSM=3.
// ---------------------------------------------------------------------------
__global__ __launch_bounds__(256, 3) void out_gemm(
    const float* __restrict__ W,    // [1024, 1024] pre-rounded
    const float* __restrict__ bias, // [1024]
    float* __restrict__ out)        // [8192, 1024]
{
    __shared__ float As[2][128][ASTR];
    __shared__ float Bs[2][16][PAD];

    const int tid = threadIdx.x;
    const int wid = tid >> 5;
    const int lane = tid & 31;
    const int g = lane >> 2;
    const int tig = lane & 3;
    const int warp_m = wid >> 1;
    const int warp_n = wid & 1;

    const int bm = blockIdx.y * 128;
    const int bn = blockIdx.x * 128;

    const int ar = tid >> 2;
    const int ac = (tid & 3) * 4;
    const int br = tid >> 5;
    const int bc = (tid & 31) * 4;

    const float* Bp0 = W + (size_t)br * CDIM + bn + bc;
    const float* Bp1 = W + (size_t)(br + 8) * CDIM + bn + bc;

    const int row0g = bm + ar;
    const int row1g = bm + ar + 64;
    const int bb0 = row0g >> 11, t0r = row0g & 2047;
    const int bb1 = row1g >> 11, t1r = row1g & 2047;

    float acc[2][8][4];
    #pragma unroll
    for (int mt = 0; mt < 2; mt++)
        #pragma unroll
        for (int nt = 0; nt < 8; nt++)
            #pragma unroll
            for (int i = 0; i < 4; i++) acc[mt][nt][i] = 0.f;

    auto issue_cp = [&](int buf, int k0) {
        const int k = k0 + ac;
        const int h = k >> 6;
        const int d = k & 63;
        cp16(&As[buf][ar][ac],
             &g_O[((bb0 * NHEAD + h) * SEQ + t0r) * HDIM + d]);
        cp16(&As[buf][ar + 64][ac],
             &g_O[((bb1 * NHEAD + h) * SEQ + t1r) * HDIM + d]);
        cp16(&Bs[buf][br][bc],     Bp0 + (size_t)k0 * CDIM);
        cp16(&Bs[buf][br + 8][bc], Bp1 + (size_t)k0 * CDIM);
        CP_COMMIT();
    };

    issue_cp(0, 0);
    CP_WAIT0();
    __syncthreads();

    const int am = warp_m * 32;
    const int an = warp_n * 64;

    int cur = 0;
    for (int k0 = 0; k0 < CDIM; k0 += 16) {
        const bool has_next = (k0 + 16) < CDIM;
        if (has_next) issue_cp(cur ^ 1, k0 + 16);

        #pragma unroll
        for (int kk = 0; kk < 16; kk += 8) {
            uint32_t Af[2][4], Bf[8][2];
            #pragma unroll
            for (int mt = 0; mt < 2; mt++) {
                const int m0 = am + mt * 16;
                Af[mt][0] = __float_as_uint(As[cur][m0 + g][kk + tig]);
                Af[mt][1] = __float_as_uint(As[cur][m0 + g + 8][kk + tig]);
                Af[mt][2] = __float_as_uint(As[cur][m0 + g][kk + tig + 4]);
                Af[mt][3] = __float_as_uint(As[cur][m0 + g + 8][kk + tig + 4]);
            }
            #pragma unroll
            for (int nt = 0; nt < 8; nt++) {
                const int n0 = an + nt * 8;
                Bf[nt][0] = __float_as_uint(Bs[cur][kk + tig][n0 + g]);
                Bf[nt][1] = __float_as_uint(Bs[cur][kk + tig + 4][n0 + g]);
            }
            #pragma unroll
            for (int mt = 0; mt < 2; mt++)
                #pragma unroll
                for (int nt = 0; nt < 8; nt++)
                    mma_tf32(acc[mt][nt], Af[mt], Bf[nt][0], Bf[nt][1]);
        }

        if (has_next) {
            CP_WAIT0();
            __syncthreads();
            cur ^= 1;
        }
    }

    #pragma unroll
    for (int mt = 0; mt < 2; mt++) {
        #pragma unroll
        for (int half = 0; half < 2; half++) {
            const int row = bm + am + mt * 16 + g + half * 8;
            #pragma unroll
            for (int nt = 0; nt < 8; nt++) {
                const int col = bn + an + nt * 8 + tig * 2;
                float v0 = acc[mt][nt][half * 2 + 0] + bias[col];
                float v1 = acc[mt][nt][half * 2 + 1] + bias[col + 1];
                *(float2*)&out[(size_t)row * CDIM + col] = make_float2(v0, v1);
            }
        }
    }
}

// ---------------------------------------------------------------------------
extern "C" void kernel_launch(void* const* d_in, const int* in_sizes, int n_in,
                              void* d_out, int out_size)
{
    const float* x     = (const float*)d_in[0];
    const float* W_qkv = (const float*)d_in[1];
    const float* b_qkv = (const float*)d_in[2];
    const float* W_out = (const float*)d_in[3];
    const float* b_out = (const float*)d_in[4];
    float* out = (float*)d_out;

    float *d_Xr, *d_Wqr, *d_Wor;
    cudaGetSymbolAddress((void**)&d_Xr,  g_Xr);
    cudaGetSymbolAddress((void**)&d_Wqr, g_Wqr);
    cudaGetSymbolAddress((void**)&d_Wor, g_Wor);

    // Idempotent; called every invocation (no static guards allowed).
    cudaFuncSetAttribute(attn_kernel,
                         cudaFuncAttributeMaxDynamicSharedMemorySize,
                         ATTN_SMEM);

    // 0) tf32 pre-rounding prepass
    round_kernel<<<2048, 256>>>(x,     d_Xr,  (BATCH * SEQ * CDIM) / 4);
    round_kernel<<<2048, 256>>>(W_qkv, d_Wqr, (CDIM * N3C) / 4);
    round_kernel<<<1024, 256>>>(W_out, d_Wor, (CDIM * CDIM) / 4);

    // 1) QKV projection
    qkv_gemm<<<dim3(N3C / 128, (BATCH * SEQ) / 128), 256>>>(d_Xr, d_Wqr, b_qkv);

    // 2) causal flash attention (pipelined staging)
    attn_kernel<<<dim3(SEQ / 128, BATCH * NHEAD), 256, ATTN_SMEM>>>();

    // 3) output projection
    out_gemm<<<dim3(CDIM / 128, (BATCH * SEQ) / 128), 256>>>(d_Wor, b_out, out);
}